// round 9
// baseline (speedup 1.0000x reference)
#include <cuda_runtime.h>
#include <cuda_fp16.h>

#define N_NODES 50000
#define N_EDGES 800000
#define D 128

#define SCAN_B 512
#define SCAN_BLOCKS ((N_NODES + SCAN_B - 1) / SCAN_B)   // 98

#define GBM 64
#define GBK 8
#define SA_PAD 4
#define GEMM_BLOCKS ((N_NODES + GBM - 1) / GBM)          // 782
#define PERM_EPT 4
#define PERM_BLOCKS ((N_EDGES + 256 * PERM_EPT - 1) / (256 * PERM_EPT))  // 782

// Scratch (static __device__ per allocation rules; zero-initialized at load)
__device__ __half g_H[N_NODES * D];       // h = x @ W in fp16  (12.8 MB)
__device__ int    g_count[N_NODES];       // self-cleaned each invocation
__device__ int    g_start[N_NODES + 1];
__device__ int    g_cursor[N_NODES];
__device__ int    g_bsum[SCAN_BLOCKS];
__device__ int2   g_edge[N_EDGES];        // {val_bits, col} sorted by row

// ---------------------------------------------------------------------------
// Histogram of row indices (int4-vectorized, 4 edges per thread)
// ---------------------------------------------------------------------------
__global__ void hist_kernel(const int* __restrict__ row) {
    int t = blockIdx.x * blockDim.x + threadIdx.x;
    if (t * 4 >= N_EDGES) return;
    int4 r = __ldg((const int4*)&row[t * 4]);
    atomicAdd(&g_count[r.x], 1);
    atomicAdd(&g_count[r.y], 1);
    atomicAdd(&g_count[r.z], 1);
    atomicAdd(&g_count[r.w], 1);
}

// ---------------------------------------------------------------------------
// Level 1: per-block sum of 512 counters
// ---------------------------------------------------------------------------
__global__ void scan_reduce_kernel() {
    __shared__ int s[SCAN_B];
    int tid = threadIdx.x;
    int i = blockIdx.x * SCAN_B + tid;
    s[tid] = (i < N_NODES) ? g_count[i] : 0;
    __syncthreads();
#pragma unroll
    for (int off = SCAN_B / 2; off > 0; off >>= 1) {
        if (tid < off) s[tid] += s[tid + off];
        __syncthreads();
    }
    if (tid == 0) g_bsum[blockIdx.x] = s[0];
}

// ---------------------------------------------------------------------------
// Level 2+3 fused: every block scans the 98 block-sums in smem,
// then its intra-block exclusive scan. Self-cleans g_count.
// ---------------------------------------------------------------------------
__global__ void scan_apply_kernel() {
    __shared__ int s[SCAN_B];
    __shared__ int sb[128];
    int tid = threadIdx.x;

    if (tid < 128) sb[tid] = (tid < SCAN_BLOCKS) ? g_bsum[tid] : 0;
    __syncthreads();
#pragma unroll
    for (int off = 1; off < 128; off <<= 1) {
        int t = (tid < 128 && tid >= off) ? sb[tid - off] : 0;
        __syncthreads();
        if (tid < 128) sb[tid] += t;
        __syncthreads();
    }
    int boff = (blockIdx.x == 0) ? 0 : sb[blockIdx.x - 1];

    int i = blockIdx.x * SCAN_B + tid;
    int c = (i < N_NODES) ? g_count[i] : 0;
    s[tid] = c;
    __syncthreads();
#pragma unroll
    for (int off = 1; off < SCAN_B; off <<= 1) {
        int t = (tid >= off) ? s[tid - off] : 0;
        __syncthreads();
        s[tid] += t;
        __syncthreads();
    }
    if (i < N_NODES) {
        int ex = boff + s[tid] - c;
        g_start[i] = ex;
        g_cursor[i] = ex;
        g_count[i] = 0;
    }
    if (blockIdx.x == 0 && tid == 0) g_start[N_NODES] = N_EDGES;
}

// ---------------------------------------------------------------------------
// FAT kernel: blocks [0, GEMM_BLOCKS) run a 64x128 GEMM tile (4x8 micro);
//             blocks [GEMM_BLOCKS, +PERM_BLOCKS) run the edge permute.
// __launch_bounds__(256, 4): cap regs at 64 so 4 CTAs/SM are resident.
// ---------------------------------------------------------------------------
__global__ void __launch_bounds__(256, 4)
gemm_permute_kernel(const float* __restrict__ X,
                    const float* __restrict__ W,
                    const int* __restrict__ row,
                    const int* __restrict__ col,
                    const float* __restrict__ vals) {
    __shared__ float sA[GBK][GBM + SA_PAD];   // X^T tile: sA[k][m]
    __shared__ float sB[GBK][D];              // W tile:   sB[k][n]
    const int tid = threadIdx.x;              // 0..255

    if (blockIdx.x < GEMM_BLOCKS) {
        const int tx = tid & 15;              // cols tx*8 .. tx*8+7
        const int ty = tid >> 4;              // rows ty*4 .. ty*4+3
        const int block_m = blockIdx.x * GBM;

        const int lr = tid >> 1;              // A row 0..63 (threads 0..127)
        const int lc = (tid & 1) * 4;         // A k offset 0 or 4
        const int wr = tid >> 5;              // B k row 0..7
        const int wc = (tid & 31) * 4;        // B n col

        float acc[4][8];
#pragma unroll
        for (int i = 0; i < 4; i++)
#pragma unroll
            for (int j = 0; j < 8; j++) acc[i][j] = 0.f;

        for (int k0 = 0; k0 < D; k0 += GBK) {
            if (tid < 128) {
                int gm = block_m + lr;
                float4 xv = make_float4(0.f, 0.f, 0.f, 0.f);
                if (gm < N_NODES) xv = *(const float4*)&X[gm * D + k0 + lc];
                sA[lc + 0][lr] = xv.x;
                sA[lc + 1][lr] = xv.y;
                sA[lc + 2][lr] = xv.z;
                sA[lc + 3][lr] = xv.w;
            }
            *(float4*)&sB[wr][wc] = *(const float4*)&W[(k0 + wr) * D + wc];
            __syncthreads();

#pragma unroll
            for (int k = 0; k < GBK; k++) {
                float a[4], b[8];
                *(float4*)&a[0] = *(const float4*)&sA[k][ty * 4];
                *(float4*)&b[0] = *(const float4*)&sB[k][tx * 8];
                *(float4*)&b[4] = *(const float4*)&sB[k][tx * 8 + 4];
#pragma unroll
                for (int i = 0; i < 4; i++)
#pragma unroll
                    for (int j = 0; j < 8; j++)
                        acc[i][j] += a[i] * b[j];
            }
            __syncthreads();
        }

#pragma unroll
        for (int i = 0; i < 4; i++) {
            int gm = block_m + ty * 4 + i;
            if (gm < N_NODES) {
                __half2 h01 = __floats2half2_rn(acc[i][0], acc[i][1]);
                __half2 h23 = __floats2half2_rn(acc[i][2], acc[i][3]);
                __half2 h45 = __floats2half2_rn(acc[i][4], acc[i][5]);
                __half2 h67 = __floats2half2_rn(acc[i][6], acc[i][7]);
                uint4 pk;
                pk.x = *(unsigned*)&h01;
                pk.y = *(unsigned*)&h23;
                pk.z = *(unsigned*)&h45;
                pk.w = *(unsigned*)&h67;
                *(uint4*)&g_H[(size_t)gm * D + tx * 8] = pk;
            }
        }
    } else {
        int b = blockIdx.x - GEMM_BLOCKS;
        int base = b * (256 * PERM_EPT) + tid;
#pragma unroll
        for (int it = 0; it < PERM_EPT; it++) {
            int e = base + it * 256;
            if (e < N_EDGES) {
                int r = row[e];
                int2 pk;
                pk.x = __float_as_int(vals[e]);
                pk.y = col[e];
                int pos = atomicAdd(&g_cursor[r], 1);
                g_edge[pos] = pk;
            }
        }
    }
}

// ---------------------------------------------------------------------------
// Fused CSR SpMM + bias + ReLU: one warp per output row.
// 16 lanes per edge, uint4 (8 halves) per lane, two edges per step,
// unroll-4 steps -> 8 edges in flight per iteration.
// ---------------------------------------------------------------------------
__global__ void spmm_kernel(const float* __restrict__ bias,
                            float* __restrict__ out) {
    int warp = (blockIdx.x * blockDim.x + threadIdx.x) >> 5;
    if (warp >= N_NODES) return;
    int lane = threadIdx.x & 31;
    int half = lane >> 4;
    int sub  = lane & 15;

    int p   = g_start[warp];
    int end = g_start[warp + 1];

    float acc[8];
#pragma unroll
    for (int j = 0; j < 8; j++) acc[j] = 0.f;

    for (; p < end; p += 8) {
        int2  e[4];
        uint4 h[4];
        float v[4];
#pragma unroll
        for (int u = 0; u < 4; u++) {
            int idx = p + u * 2 + half;
            int idxc = (idx < end) ? idx : p;
            e[u] = __ldg(&g_edge[idxc]);
            v[u] = (idx < end) ? __int_as_float(e[u].x) : 0.f;
        }
#pragma unroll
        for (int u = 0; u < 4; u++)
            h[u] = __ldg((const uint4*)&g_H[(size_t)e[u].y * D + sub * 8]);
#pragma unroll
        for (int u = 0; u < 4; u++) {
            float2 f0 = __half22float2(*(__half2*)&h[u].x);
            float2 f1 = __half22float2(*(__half2*)&h[u].y);
            float2 f2 = __half22float2(*(__half2*)&h[u].z);
            float2 f3 = __half22float2(*(__half2*)&h[u].w);
            acc[0] += v[u] * f0.x; acc[1] += v[u] * f0.y;
            acc[2] += v[u] * f1.x; acc[3] += v[u] * f1.y;
            acc[4] += v[u] * f2.x; acc[5] += v[u] * f2.y;
            acc[6] += v[u] * f3.x; acc[7] += v[u] * f3.y;
        }
    }

#pragma unroll
    for (int j = 0; j < 8; j++)
        acc[j] += __shfl_xor_sync(0xffffffffu, acc[j], 16);

    if (half == 0) {
        float4 b0 = *(const float4*)&bias[sub * 8];
        float4 b1 = *(const float4*)&bias[sub * 8 + 4];
        float4 r0, r1;
        r0.x = fmaxf(acc[0] + b0.x, 0.f);
        r0.y = fmaxf(acc[1] + b0.y, 0.f);
        r0.z = fmaxf(acc[2] + b0.z, 0.f);
        r0.w = fmaxf(acc[3] + b0.w, 0.f);
        r1.x = fmaxf(acc[4] + b1.x, 0.f);
        r1.y = fmaxf(acc[5] + b1.y, 0.f);
        r1.z = fmaxf(acc[6] + b1.z, 0.f);
        r1.w = fmaxf(acc[7] + b1.w, 0.f);
        *(float4*)&out[(size_t)warp * D + sub * 8]     = r0;
        *(float4*)&out[(size_t)warp * D + sub * 8 + 4] = r1;
    }
}

// ---------------------------------------------------------------------------
// Launch
// ---------------------------------------------------------------------------
extern "C" void kernel_launch(void* const* d_in, const int* in_sizes, int n_in,
                              void* d_out, int out_size) {
    const float* x      = (const float*)d_in[0];   // [50000,128]
    const float* weight = (const float*)d_in[1];   // [128,128]
    const float* bias   = (const float*)d_in[2];   // [128]
    const float* vals   = (const float*)d_in[3];   // [800000]
    const int*   row    = (const int*)d_in[4];     // [800000]
    const int*   col    = (const int*)d_in[5];     // [800000]
    float* out = (float*)d_out;                    // [50000,128]

    // 1) CSR offsets (g_count self-cleaned by scan_apply)
    hist_kernel<<<(N_EDGES / 4 + 255) / 256, 256>>>(row);
    scan_reduce_kernel<<<SCAN_BLOCKS, SCAN_B>>>();
    scan_apply_kernel<<<SCAN_BLOCKS, SCAN_B>>>();

    // 2) GEMM and edge-permute co-scheduled in one launch (high occupancy)
    gemm_permute_kernel<<<GEMM_BLOCKS + PERM_BLOCKS, 256>>>(x, weight,
                                                            row, col, vals);

    // 3) fused SpMM + bias + ReLU
    spmm_kernel<<<(N_NODES + 7) / 8, 256>>>(bias, out);
}

// round 10
// speedup vs baseline: 1.7273x; 1.7273x over previous
#include <cuda_runtime.h>
#include <cuda_fp16.h>

#define N_NODES 50000
#define N_EDGES 800000
#define D 128

#define SCAN_B 512
#define SCAN_BLOCKS ((N_NODES + SCAN_B - 1) / SCAN_B)   // 98

#define TM 128                                            // GEMM rows per block
#define GEMM_BLOCKS ((N_NODES + TM - 1) / TM)             // 391
#define PERM_EPT 4
#define PERM_BLOCKS ((N_EDGES + 256 * PERM_EPT - 1) / (256 * PERM_EPT))  // 782
#define HIST_BLOCKS ((N_EDGES / 4 + 255) / 256)           // 782
#define WCONV_BLOCKS 8
#define SPITCH 24   // smem row pitch in halves: 48B = 12 banks -> conflict-free frags

// Scratch (static __device__ per allocation rules; zero-initialized at load)
__device__ __half g_H[N_NODES * D];       // h = x @ W in fp16  (12.8 MB)
__device__ __half g_WT[D * D];            // W^T in fp16, [n][k]
__device__ int    g_count[N_NODES];       // self-cleaned each invocation
__device__ int    g_start[N_NODES + 1];
__device__ int    g_cursor[N_NODES];
__device__ int    g_bsum[SCAN_BLOCKS];
__device__ int2   g_edge[N_EDGES];        // {val_bits, col} sorted by row

// ---------------------------------------------------------------------------
// Histogram (int4, 4 edges/thread) + W transpose/convert, one launch
// ---------------------------------------------------------------------------
__global__ void hist_wconv_kernel(const int* __restrict__ row,
                                  const float* __restrict__ W) {
    if (blockIdx.x < HIST_BLOCKS) {
        int t = blockIdx.x * blockDim.x + threadIdx.x;
        if (t * 4 >= N_EDGES) return;
        int4 r = __ldg((const int4*)&row[t * 4]);
        atomicAdd(&g_count[r.x], 1);
        atomicAdd(&g_count[r.y], 1);
        atomicAdd(&g_count[r.z], 1);
        atomicAdd(&g_count[r.w], 1);
    } else {
        int b = blockIdx.x - HIST_BLOCKS;
        int base = (b * 256 + threadIdx.x) * 8;
#pragma unroll
        for (int i = 0; i < 8; i++) {
            int idx = base + i;               // linear over g_WT [n*128+k]
            int n = idx >> 7, k = idx & 127;
            g_WT[idx] = __float2half_rn(W[k * D + n]);
        }
    }
}

// ---------------------------------------------------------------------------
// Level 1: per-block sum of 512 counters
// ---------------------------------------------------------------------------
__global__ void scan_reduce_kernel() {
    __shared__ int s[SCAN_B];
    int tid = threadIdx.x;
    int i = blockIdx.x * SCAN_B + tid;
    s[tid] = (i < N_NODES) ? g_count[i] : 0;
    __syncthreads();
#pragma unroll
    for (int off = SCAN_B / 2; off > 0; off >>= 1) {
        if (tid < off) s[tid] += s[tid + off];
        __syncthreads();
    }
    if (tid == 0) g_bsum[blockIdx.x] = s[0];
}

// ---------------------------------------------------------------------------
// Level 2+3 fused scan; self-cleans g_count
// ---------------------------------------------------------------------------
__global__ void scan_apply_kernel() {
    __shared__ int s[SCAN_B];
    __shared__ int sb[128];
    int tid = threadIdx.x;

    if (tid < 128) sb[tid] = (tid < SCAN_BLOCKS) ? g_bsum[tid] : 0;
    __syncthreads();
#pragma unroll
    for (int off = 1; off < 128; off <<= 1) {
        int t = (tid < 128 && tid >= off) ? sb[tid - off] : 0;
        __syncthreads();
        if (tid < 128) sb[tid] += t;
        __syncthreads();
    }
    int boff = (blockIdx.x == 0) ? 0 : sb[blockIdx.x - 1];

    int i = blockIdx.x * SCAN_B + tid;
    int c = (i < N_NODES) ? g_count[i] : 0;
    s[tid] = c;
    __syncthreads();
#pragma unroll
    for (int off = 1; off < SCAN_B; off <<= 1) {
        int t = (tid >= off) ? s[tid - off] : 0;
        __syncthreads();
        s[tid] += t;
        __syncthreads();
    }
    if (i < N_NODES) {
        int ex = boff + s[tid] - c;
        g_start[i] = ex;
        g_cursor[i] = ex;
        g_count[i] = 0;
    }
    if (blockIdx.x == 0 && tid == 0) g_start[N_NODES] = N_EDGES;
}

// ---------------------------------------------------------------------------
// FAT kernel: blocks [0, GEMM_BLOCKS): tensor-core GEMM (fp16 mma, fp32 acc);
//             blocks [GEMM_BLOCKS, +PERM_BLOCKS): edge permute.
// Warp tile: 16 rows x 128 cols = 16 x m16n8k16 mma per k-chunk.
// ---------------------------------------------------------------------------
__global__ void __launch_bounds__(256)
gemm_permute_kernel(const float* __restrict__ X,
                    const int* __restrict__ row,
                    const int* __restrict__ col,
                    const float* __restrict__ vals) {
    __shared__ __half sX[TM][SPITCH];    // [m][k16]
    __shared__ __half sW[D][SPITCH];     // [n][k16]  (W^T chunk)
    const int tid = threadIdx.x;

    if (blockIdx.x < GEMM_BLOCKS) {
        const int wid  = tid >> 5;
        const int lane = tid & 31;
        const int g    = lane >> 2;       // group id 0..7
        const int t4   = lane & 3;        // thread-in-group 0..3
        const int block_m = blockIdx.x * TM;
        const int wrow = wid * 16;

        float c[16][4];
#pragma unroll
        for (int nt = 0; nt < 16; nt++)
#pragma unroll
            for (int j = 0; j < 4; j++) c[nt][j] = 0.f;

        for (int kt = 0; kt < 8; kt++) {
            int k0 = kt * 16;
            // stage X chunk: 128 rows x 16 k, fp32 -> fp16
#pragma unroll
            for (int i = 0; i < 2; i++) {
                int idx = tid + i * 256;          // 0..511
                int r = idx >> 2;
                int kq = (idx & 3) * 4;
                int gm = block_m + r;
                float4 xv = make_float4(0.f, 0.f, 0.f, 0.f);
                if (gm < N_NODES)
                    xv = *(const float4*)&X[gm * D + k0 + kq];
                *(__half2*)&sX[r][kq]     = __floats2half2_rn(xv.x, xv.y);
                *(__half2*)&sX[r][kq + 2] = __floats2half2_rn(xv.z, xv.w);
            }
            // stage W^T chunk: 128 n x 16 k (copy 8 halves per thread)
            {
                int n = tid >> 1;
                int kk = (tid & 1) * 8;
                uint4 w = *(const uint4*)&g_WT[n * D + k0 + kk];
                *(uint4*)&sW[n][kk] = w;
            }
            __syncthreads();

            // A fragment (m16 x k16), rows wrow+g / wrow+g+8
            unsigned a0 = *(unsigned*)&sX[wrow + g][t4 * 2];
            unsigned a1 = *(unsigned*)&sX[wrow + g + 8][t4 * 2];
            unsigned a2 = *(unsigned*)&sX[wrow + g][t4 * 2 + 8];
            unsigned a3 = *(unsigned*)&sX[wrow + g + 8][t4 * 2 + 8];

#pragma unroll
            for (int nt = 0; nt < 16; nt++) {
                unsigned b0 = *(unsigned*)&sW[nt * 8 + g][t4 * 2];
                unsigned b1 = *(unsigned*)&sW[nt * 8 + g][t4 * 2 + 8];
                asm volatile(
                    "mma.sync.aligned.m16n8k16.row.col.f32.f16.f16.f32 "
                    "{%0,%1,%2,%3}, {%4,%5,%6,%7}, {%8,%9}, {%0,%1,%2,%3};"
                    : "+f"(c[nt][0]), "+f"(c[nt][1]),
                      "+f"(c[nt][2]), "+f"(c[nt][3])
                    : "r"(a0), "r"(a1), "r"(a2), "r"(a3), "r"(b0), "r"(b1));
            }
            __syncthreads();
        }

        // store H in fp16: c0,c1 -> row g, cols 2t..2t+1; c2,c3 -> row g+8
        int r0 = block_m + wrow + g;
        int r1 = r0 + 8;
#pragma unroll
        for (int nt = 0; nt < 16; nt++) {
            int ccol = nt * 8 + t4 * 2;
            if (r0 < N_NODES)
                *(__half2*)&g_H[(size_t)r0 * D + ccol] =
                    __floats2half2_rn(c[nt][0], c[nt][1]);
            if (r1 < N_NODES)
                *(__half2*)&g_H[(size_t)r1 * D + ccol] =
                    __floats2half2_rn(c[nt][2], c[nt][3]);
        }
    } else {
        int b = blockIdx.x - GEMM_BLOCKS;
        int base = b * (256 * PERM_EPT) + tid;
#pragma unroll
        for (int it = 0; it < PERM_EPT; it++) {
            int e = base + it * 256;
            if (e < N_EDGES) {
                int r = row[e];
                int2 pk;
                pk.x = __float_as_int(vals[e]);
                pk.y = col[e];
                int pos = atomicAdd(&g_cursor[r], 1);
                g_edge[pos] = pk;
            }
        }
    }
}

// ---------------------------------------------------------------------------
// Fused CSR SpMM + bias + ReLU: one warp per output row.
// 16 lanes per edge, uint4 (8 halves) per lane, two edges per step.
// ---------------------------------------------------------------------------
__global__ void spmm_kernel(const float* __restrict__ bias,
                            float* __restrict__ out) {
    int warp = (blockIdx.x * blockDim.x + threadIdx.x) >> 5;
    if (warp >= N_NODES) return;
    int lane = threadIdx.x & 31;
    int half = lane >> 4;
    int sub  = lane & 15;

    int p   = g_start[warp];
    int end = g_start[warp + 1];

    float acc[8];
#pragma unroll
    for (int j = 0; j < 8; j++) acc[j] = 0.f;

    for (; p < end; p += 8) {
        int2  e[4];
        uint4 h[4];
        float v[4];
#pragma unroll
        for (int u = 0; u < 4; u++) {
            int idx = p + u * 2 + half;
            int idxc = (idx < end) ? idx : p;
            e[u] = __ldg(&g_edge[idxc]);
            v[u] = (idx < end) ? __int_as_float(e[u].x) : 0.f;
        }
#pragma unroll
        for (int u = 0; u < 4; u++)
            h[u] = __ldg((const uint4*)&g_H[(size_t)e[u].y * D + sub * 8]);
#pragma unroll
        for (int u = 0; u < 4; u++) {
            float2 f0 = __half22float2(*(__half2*)&h[u].x);
            float2 f1 = __half22float2(*(__half2*)&h[u].y);
            float2 f2 = __half22float2(*(__half2*)&h[u].z);
            float2 f3 = __half22float2(*(__half2*)&h[u].w);
            acc[0] += v[u] * f0.x; acc[1] += v[u] * f0.y;
            acc[2] += v[u] * f1.x; acc[3] += v[u] * f1.y;
            acc[4] += v[u] * f2.x; acc[5] += v[u] * f2.y;
            acc[6] += v[u] * f3.x; acc[7] += v[u] * f3.y;
        }
    }

#pragma unroll
    for (int j = 0; j < 8; j++)
        acc[j] += __shfl_xor_sync(0xffffffffu, acc[j], 16);

    if (half == 0) {
        float4 b0 = *(const float4*)&bias[sub * 8];
        float4 b1 = *(const float4*)&bias[sub * 8 + 4];
        float4 r0, r1;
        r0.x = fmaxf(acc[0] + b0.x, 0.f);
        r0.y = fmaxf(acc[1] + b0.y, 0.f);
        r0.z = fmaxf(acc[2] + b0.z, 0.f);
        r0.w = fmaxf(acc[3] + b0.w, 0.f);
        r1.x = fmaxf(acc[4] + b1.x, 0.f);
        r1.y = fmaxf(acc[5] + b1.y, 0.f);
        r1.z = fmaxf(acc[6] + b1.z, 0.f);
        r1.w = fmaxf(acc[7] + b1.w, 0.f);
        *(float4*)&out[(size_t)warp * D + sub * 8]     = r0;
        *(float4*)&out[(size_t)warp * D + sub * 8 + 4] = r1;
    }
}

// ---------------------------------------------------------------------------
// Launch
// ---------------------------------------------------------------------------
extern "C" void kernel_launch(void* const* d_in, const int* in_sizes, int n_in,
                              void* d_out, int out_size) {
    const float* x      = (const float*)d_in[0];   // [50000,128]
    const float* weight = (const float*)d_in[1];   // [128,128]
    const float* bias   = (const float*)d_in[2];   // [128]
    const float* vals   = (const float*)d_in[3];   // [800000]
    const int*   row    = (const int*)d_in[4];     // [800000]
    const int*   col    = (const int*)d_in[5];     // [800000]
    float* out = (float*)d_out;                    // [50000,128]

    // 1) histogram + W transpose/convert (one launch), then scan
    hist_wconv_kernel<<<HIST_BLOCKS + WCONV_BLOCKS, 256>>>(row, weight);
    scan_reduce_kernel<<<SCAN_BLOCKS, SCAN_B>>>();
    scan_apply_kernel<<<SCAN_BLOCKS, SCAN_B>>>();

    // 2) tensor-core GEMM + edge permute co-scheduled
    gemm_permute_kernel<<<GEMM_BLOCKS + PERM_BLOCKS, 256>>>(x, row, col, vals);

    // 3) fused SpMM + bias + ReLU
    spmm_kernel<<<(N_NODES + 7) / 8, 256>>>(bias, out);
}